// round 13
// baseline (speedup 1.0000x reference)
#include <cuda_runtime.h>

#define FULL 0xffffffffu

__device__ __forceinline__ float sigmoidf_(float y) {
    return __fdividef(1.f, 1.f + __expf(-y));
}

// ---- packed f32x2 helpers (sm_103a FFMA2 path) ----
__device__ __forceinline__ unsigned long long pack2_(float a, float b) {
    unsigned long long r;
    asm("mov.b64 %0, {%1, %2};" : "=l"(r) : "f"(a), "f"(b));
    return r;
}
__device__ __forceinline__ void fma2_(unsigned long long& d,
                                      unsigned long long a, unsigned long long b) {
    asm("fma.rn.f32x2 %0, %1, %2, %0;" : "+l"(d) : "l"(a), "l"(b));
}
__device__ __forceinline__ float sum2_(unsigned long long v) {
    float lo, hi;
    asm("mov.b64 {%0, %1}, %2;" : "=f"(lo), "=f"(hi) : "l"(v));
    return lo + hi;
}

#define XPAD 68   // row padding: stride 272B, kills cross-row bank aliasing

// KGCN fused: one CTA per FOUR batch elements, 256 threads, 4 CTAs/SM.
// Phase C: balanced half-warp task map. Matvec: warp-autonomous packed FMA;
// d-half 1 iterates chunks in ROTATED order ((q+1)&7) so the two 16-lane
// halves never hit the same smem banks -> 1 wavefront per LDS instead of 2.
__global__ void __launch_bounds__(256, 4) kgcn_kernel(
    const int* __restrict__ U, const int* __restrict__ V,
    const int* __restrict__ adj_ent, const int* __restrict__ adj_rel,
    const float* __restrict__ usr_emb, const float* __restrict__ rel_emb,
    const float* __restrict__ ent_emb, const float* __restrict__ Wg,
    const float* __restrict__ bg, float* __restrict__ out, int NR)
{
    __shared__ float user_sh[4][64];
    __shared__ float urel_sh[4][32];
    __shared__ int   nbr_sh[4][272];   // [0..255] hop2 ents, [256..271] hop1 ents
    __shared__ int   rel_sh[4][272];
    __shared__ float attn16_sh[4][16];
    __shared__ int   v_sh[4];
    __shared__ __align__(16) float x_sh[4][17][XPAD];  // pre-matvec activations
    __shared__ __align__(16) float h_sh[4][17][XPAD];  // post-sigmoid outputs
    __shared__ __align__(16) float x2_sh[4][XPAD];
    __shared__ float red2_sh[4][4];

    const int tid   = threadIdx.x;
    const int col   = tid & 63;
    const int lane  = tid & 31;
    const int w     = tid >> 5;
    const int chunk = w & 3;          // 16-col chunk owned by this warp (matvec)
    const int par   = w >> 2;         // row parity (matvec)
    const int halfL = lane >> 4;      // d-half within warp (matvec)
    const int k15w  = lane & 15;
    const int mycol = chunk * 16 + k15w;

    const int b0 = 4 * blockIdx.x;
    int uu[4], vv[4];
    #pragma unroll
    for (int e = 0; e < 4; e++) { uu[e] = U[b0 + e]; vv[e] = V[b0 + e]; }

    // ---- Phase A: stage users, v, hop-1 adjacency ----
    user_sh[tid >> 6][col] = usr_emb[uu[tid >> 6] * 64 + col];
    if (tid < 4) v_sh[tid] = vv[tid];
    if (tid < 64) {
        int e = tid >> 4, j = tid & 15;
        nbr_sh[e][256 + j] = adj_ent[vv[e] * 16 + j];
        rel_sh[e][256 + j] = adj_rel[vv[e] * 16 + j];
    }
    __syncthreads();

    // ---- Phase B: hop-2 adjacency (4 elems) + urel tables ----
    {
        int j = tid & 15, pr = tid >> 4;
        #pragma unroll
        for (int e = 0; e < 4; e++) {
            int p = nbr_sh[e][256 + pr];
            nbr_sh[e][tid] = adj_ent[p * 16 + j];
            rel_sh[e][tid] = adj_rel[p * 16 + j];
        }
    }
    {
        int r = tid >> 3;
        int c = (tid & 7) * 8;
        float pa[4] = {0.f, 0.f, 0.f, 0.f};
        if (r < NR) {
            const float4* rp = (const float4*)(rel_emb + r * 64 + c);
            float4 aa = rp[0], bb = rp[1];
            #pragma unroll
            for (int e = 0; e < 4; e++)
                pa[e] = aa.x * user_sh[e][c+0] + aa.y * user_sh[e][c+1]
                      + aa.z * user_sh[e][c+2] + aa.w * user_sh[e][c+3]
                      + bb.x * user_sh[e][c+4] + bb.y * user_sh[e][c+5]
                      + bb.z * user_sh[e][c+6] + bb.w * user_sh[e][c+7];
        }
        #pragma unroll
        for (int o = 4; o > 0; o >>= 1) {
            #pragma unroll
            for (int e = 0; e < 4; e++)
                pa[e] += __shfl_down_sync(FULL, pa[e], o);
        }
        if ((tid & 7) == 0 && r < NR) {
            #pragma unroll
            for (int e = 0; e < 4; e++) urel_sh[e][r] = pa[e];
        }
    }
    __syncthreads();

    // ---- Phase C: balanced half-warp tasks ----
    {
        const int hlf16 = lane & 16;
        const int k15   = lane & 15;
        const int hw    = 2 * w + halfL;      // half-warp id 0..15
        const int e     = hw & 3;             // element owned by this half-warp
        const int rbase = hw >> 2;            // base row (rows rbase, +4, +8, +12)
        const ulonglong2* entu2 = (const ulonglong2*)ent_emb;

        // self-initialized accumulators: loads issue before the softmax chains
        unsigned long long accA[4], accB[4];
        #pragma unroll
        for (int i = 0; i < 4; i++) {
            int r = rbase + 4 * i;
            ulonglong2 sv = entu2[(nbr_sh[e][256 + r] << 4) + k15];
            accA[i] = sv.x; accB[i] = sv.y;
        }

        // softmax for the 4 rows (independent chains, width-16 butterflies)
        float sc[4], mx[4], ev[4], sm[4], pp[4];
        #pragma unroll
        for (int i = 0; i < 4; i++)
            sc[i] = urel_sh[e][rel_sh[e][((rbase + 4 * i) << 4) + k15]];
        #pragma unroll
        for (int i = 0; i < 4; i++) mx[i] = sc[i];
        #pragma unroll
        for (int o = 8; o > 0; o >>= 1) {
            #pragma unroll
            for (int i = 0; i < 4; i++)
                mx[i] = fmaxf(mx[i], __shfl_xor_sync(FULL, mx[i], o));
        }
        #pragma unroll
        for (int i = 0; i < 4; i++) { ev[i] = __expf(sc[i] - mx[i]); sm[i] = ev[i]; }
        #pragma unroll
        for (int o = 8; o > 0; o >>= 1) {
            #pragma unroll
            for (int i = 0; i < 4; i++)
                sm[i] += __shfl_xor_sync(FULL, sm[i], o);
        }
        #pragma unroll
        for (int i = 0; i < 4; i++) pp[i] = __fdividef(ev[i], sm[i]);

        const int* nb[4];
        #pragma unroll
        for (int i = 0; i < 4; i++) nb[i] = &nbr_sh[e][(rbase + 4 * i) << 4];
        #pragma unroll
        for (int k = 0; k < 16; k++) {
            #pragma unroll
            for (int i = 0; i < 4; i++) {
                float pk = __shfl_sync(FULL, pp[i], hlf16 + k);
                unsigned long long pkk = pack2_(pk, pk);
                ulonglong2 t = entu2[(nb[i][k] << 4) + k15];
                fma2_(accA[i], pkk, t.x);
                fma2_(accB[i], pkk, t.y);
            }
        }
        #pragma unroll
        for (int i = 0; i < 4; i++) {
            ulonglong2 o2; o2.x = accA[i]; o2.y = accB[i];
            ((ulonglong2*)x_sh[e][rbase + 4 * i])[k15] = o2;
        }

        // hop-0 rows: half-warps 0..3 each take ONE hop-0 row (no dup halves)
        if (hw < 4) {
            const int e2 = hw;
            unsigned long long a2A, a2B;
            {
                ulonglong2 sv2 = entu2[(v_sh[e2] << 4) + k15];
                a2A = sv2.x; a2B = sv2.y;
            }
            float s2 = urel_sh[e2][rel_sh[e2][256 + k15]];
            float mx2 = s2;
            mx2 = fmaxf(mx2, __shfl_xor_sync(FULL, mx2, 8));
            mx2 = fmaxf(mx2, __shfl_xor_sync(FULL, mx2, 4));
            mx2 = fmaxf(mx2, __shfl_xor_sync(FULL, mx2, 2));
            mx2 = fmaxf(mx2, __shfl_xor_sync(FULL, mx2, 1));
            float ev2 = __expf(s2 - mx2);
            float sm2 = ev2;
            sm2 += __shfl_xor_sync(FULL, sm2, 8);
            sm2 += __shfl_xor_sync(FULL, sm2, 4);
            sm2 += __shfl_xor_sync(FULL, sm2, 2);
            sm2 += __shfl_xor_sync(FULL, sm2, 1);
            float p2 = __fdividef(ev2, sm2);
            attn16_sh[e2][k15] = p2;

            #pragma unroll
            for (int k = 0; k < 16; k++) {
                float pk = __shfl_sync(FULL, p2, hlf16 + k);
                unsigned long long pkk = pack2_(pk, pk);
                ulonglong2 t = entu2[(nbr_sh[e2][256 + k] << 4) + k15];
                fma2_(a2A, pkk, t.x);
                fma2_(a2B, pkk, t.y);
            }
            ulonglong2 o2; o2.x = a2A; o2.y = a2B;
            ((ulonglong2*)x_sh[e2][16])[k15] = o2;
        }
    }

    // ---- W half-column -> packed regs (after Phase C: lifetimes don't stack) ----
    unsigned long long Wp[16];   // Wp[i] packs W cols (2i, 2i+1) of my half
    #pragma unroll
    for (int i = 0; i < 16; i++) {
        float wa = Wg[(halfL * 32 + 2 * i) * 64 + mycol];
        float wb = Wg[(halfL * 32 + 2 * i + 1) * 64 + mycol];
        Wp[i] = pack2_(wa, wb);
    }
    const float bmy = bg[mycol];
    __syncthreads();

    // ---- Matvec: warp-autonomous, packed FMA; half 1 iterates chunks in
    //      rotated order so both halves hit disjoint banks (1 wf per LDS). ----
    {
        for (int rr = par; rr <= 16; rr += 2) {
            unsigned long long A0 = 0ull, A1 = 0ull, A2 = 0ull, A3 = 0ull;
            #pragma unroll
            for (int q = 0; q < 8; q++) {
                const int qe  = (q + halfL) & 7;        // rotation for half 1
                const int off = halfL * 32 + 4 * qe;
                ulonglong2 v0 = *(const ulonglong2*)&x_sh[0][rr][off];
                ulonglong2 v1 = *(const ulonglong2*)&x_sh[1][rr][off];
                ulonglong2 v2 = *(const ulonglong2*)&x_sh[2][rr][off];
                ulonglong2 v3 = *(const ulonglong2*)&x_sh[3][rr][off];
                fma2_(A0, v0.x, Wp[2*qe]); fma2_(A0, v0.y, Wp[2*qe+1]);
                fma2_(A1, v1.x, Wp[2*qe]); fma2_(A1, v1.y, Wp[2*qe+1]);
                fma2_(A2, v2.x, Wp[2*qe]); fma2_(A2, v2.y, Wp[2*qe+1]);
                fma2_(A3, v3.x, Wp[2*qe]); fma2_(A3, v3.y, Wp[2*qe+1]);
            }
            float y0 = sum2_(A0), y1 = sum2_(A1), y2 = sum2_(A2), y3 = sum2_(A3);
            float t0 = y0 + __shfl_xor_sync(FULL, y0, 16);
            float t1 = y1 + __shfl_xor_sync(FULL, y1, 16);
            float t2 = y2 + __shfl_xor_sync(FULL, y2, 16);
            float t3 = y3 + __shfl_xor_sync(FULL, y3, 16);
            if (halfL == 0) {
                h_sh[0][rr][mycol] = sigmoidf_(t0 + bmy);
                h_sh[1][rr][mycol] = sigmoidf_(t1 + bmy);
                h_sh[2][rr][mycol] = sigmoidf_(t2 + bmy);
                h_sh[3][rr][mycol] = sigmoidf_(t3 + bmy);
            }
        }
    }
    __syncthreads();

    // ---- Phase D: iter-1 agg (thread per (e,col)) ----
    {
        const int e = tid >> 6;
        float a0 = 0.f, a1 = 0.f, a2 = 0.f, a3 = 0.f;
        #pragma unroll
        for (int k = 0; k < 16; k += 4) {
            a0 = fmaf(attn16_sh[e][k + 0], h_sh[e][k + 0][col], a0);
            a1 = fmaf(attn16_sh[e][k + 1], h_sh[e][k + 1][col], a1);
            a2 = fmaf(attn16_sh[e][k + 2], h_sh[e][k + 2][col], a2);
            a3 = fmaf(attn16_sh[e][k + 3], h_sh[e][k + 3][col], a3);
        }
        x2_sh[e][col] = h_sh[e][16][col] + ((a0 + a1) + (a2 + a3));
    }
    __syncthreads();

    // ---- Final matvec + tanh + dot(user) — warp-autonomous, rotated too ----
    {
        for (int e = par; e < 4; e += 2) {
            unsigned long long Acc = 0ull;
            #pragma unroll
            for (int q = 0; q < 8; q++) {
                const int qe  = (q + halfL) & 7;
                const int off = halfL * 32 + 4 * qe;
                ulonglong2 v = *(const ulonglong2*)&x2_sh[e][off];
                fma2_(Acc, v.x, Wp[2*qe]);
                fma2_(Acc, v.y, Wp[2*qe+1]);
            }
            float y = sum2_(Acc);
            float tot = y + __shfl_xor_sync(FULL, y, 16);
            float item = tanhf(tot + bmy);
            float t = user_sh[e][mycol] * item;   // lanes L, L+16 duplicate
            t += __shfl_xor_sync(FULL, t, 8);
            t += __shfl_xor_sync(FULL, t, 4);
            t += __shfl_xor_sync(FULL, t, 2);
            t += __shfl_xor_sync(FULL, t, 1);
            if (lane == 0) red2_sh[e][chunk] = t;  // sum of this chunk's 16 cols
        }
    }
    __syncthreads();
    if (tid < 4)
        out[b0 + tid] = sigmoidf_((red2_sh[tid][0] + red2_sh[tid][1]) +
                                  (red2_sh[tid][2] + red2_sh[tid][3]));
}

extern "C" void kernel_launch(void* const* d_in, const int* in_sizes, int n_in,
                              void* d_out, int out_size) {
    const int*   U       = (const int*)d_in[0];
    const int*   V       = (const int*)d_in[1];
    const int*   adj_ent = (const int*)d_in[2];
    const int*   adj_rel = (const int*)d_in[3];
    const float* usr_emb = (const float*)d_in[4];
    const float* rel_emb = (const float*)d_in[5];
    const float* ent_emb = (const float*)d_in[6];
    const float* W       = (const float*)d_in[7];
    const float* bvec    = (const float*)d_in[8];
    float* out = (float*)d_out;

    const int B  = in_sizes[0];
    const int NR = in_sizes[5] / 64;

    kgcn_kernel<<<B / 4, 256>>>(U, V, adj_ent, adj_rel, usr_emb, rel_emb,
                                ent_emb, W, bvec, out, NR);
}